// round 2
// baseline (speedup 1.0000x reference)
#include <cuda_runtime.h>
#include <cuda_bf16.h>

// Problem constants (Query2Context_15539191677614)
#define T_LEN 16384
#define J_LEN 64
#define D_LEN 1024

// Scratch (no cudaMalloc allowed)
__device__ float g_e[T_LEN];     // exp(rowmax)
__device__ float g_ctx[D_LEN];   // accumulated context vector
__device__ float g_S;            // sum of exps

// ---------------------------------------------------------------------------
// Kernel 0: zero the accumulators (graph replays reuse device globals)
// ---------------------------------------------------------------------------
__global__ void k_zero() {
    int i = threadIdx.x;
    if (i < D_LEN) g_ctx[i] = 0.0f;
    if (i == 0) g_S = 0.0f;
}

// ---------------------------------------------------------------------------
// Kernel 1: per-row max over J=64, e[t] = exp(max), block-partial sum -> g_S
// One warp per row; each lane loads a float2 (64 floats/row = 256B coalesced).
// ---------------------------------------------------------------------------
__global__ void k_rowmax(const float* __restrict__ s) {
    const int warpId = threadIdx.x >> 5;
    const int lane   = threadIdx.x & 31;
    const int t      = blockIdx.x * 8 + warpId;   // 8 warps/block

    const float2 v = *reinterpret_cast<const float2*>(s + (size_t)t * J_LEN + lane * 2);
    float m = fmaxf(v.x, v.y);
    #pragma unroll
    for (int off = 16; off > 0; off >>= 1)
        m = fmaxf(m, __shfl_xor_sync(0xFFFFFFFFu, m, off));

    __shared__ float sh[8];
    if (lane == 0) {
        float e = expf(m);
        g_e[t]  = e;
        sh[warpId] = e;
    }
    __syncthreads();
    if (threadIdx.x == 0) {
        float bs = 0.0f;
        #pragma unroll
        for (int w = 0; w < 8; w++) bs += sh[w];
        atomicAdd(&g_S, bs);
    }
}

// ---------------------------------------------------------------------------
// Kernel 2: ctx[k] += sum over a 64-row chunk of e[t] * h[t,k]
// 1024 threads/block (k = tid), 256 blocks; each iter streams contiguous 4KB.
// ---------------------------------------------------------------------------
__global__ __launch_bounds__(1024, 1)
void k_ctx(const float* __restrict__ h) {
    const int k  = threadIdx.x;
    const int t0 = blockIdx.x * 64;
    float acc = 0.0f;
    #pragma unroll 8
    for (int r = 0; r < 64; r++) {
        const int t = t0 + r;
        acc = fmaf(g_e[t], __ldg(h + (size_t)t * D_LEN + k), acc);
    }
    atomicAdd(&g_ctx[k], acc);
}

// ---------------------------------------------------------------------------
// Kernel 3: normalize ctx by S
// ---------------------------------------------------------------------------
__global__ void k_norm() {
    int i = threadIdx.x;
    if (i < D_LEN) g_ctx[i] = g_ctx[i] / g_S;
}

// ---------------------------------------------------------------------------
// Kernel 4: broadcast ctx[k] across T -> out[k, t], float4 streaming stores
// out is [D_LEN, T_LEN] row-major; T_LEN/4 = 4096 float4 per row.
// ---------------------------------------------------------------------------
__global__ __launch_bounds__(256)
void k_bcast(float4* __restrict__ out) {
    const int i = blockIdx.x * blockDim.x + threadIdx.x;   // < D*T/4 = 4194304
    const int k = i >> 12;                                  // / (T_LEN/4)
    const float v = g_ctx[k];
    out[i] = make_float4(v, v, v, v);
}

// ---------------------------------------------------------------------------
extern "C" void kernel_launch(void* const* d_in, const int* in_sizes, int n_in,
                              void* d_out, int out_size) {
    const float* h = (const float*)d_in[0];   // [1, T, d]
    const float* s = (const float*)d_in[1];   // [T, J]
    float* out = (float*)d_out;               // [d, T]

    k_zero<<<1, 1024>>>();
    k_rowmax<<<T_LEN / 8, 256>>>(s);
    k_ctx<<<256, 1024>>>(h);
    k_norm<<<1, 1024>>>();
    k_bcast<<<(D_LEN * T_LEN / 4) / 256, 256>>>((float4*)out);
}

// round 3
// speedup vs baseline: 1.1712x; 1.1712x over previous
#include <cuda_runtime.h>
#include <cuda_bf16.h>

// Problem constants (Query2Context_15539191677614)
#define T_LEN 16384
#define J_LEN 64
#define D_LEN 1024
#define GRID1 296   // 2 CTAs per SM (148 SMs), balanced row split

// Scratch (no cudaMalloc allowed; overwritten every replay -> deterministic)
__device__ float g_partial[GRID1 * D_LEN];  // per-block ctx partials
__device__ float g_bsum[GRID1];             // per-block exp sums

// ---------------------------------------------------------------------------
// Kernel 1: fused rowmax/exp + weighted-sum partials.
// Block b owns rows [t0, t1): computes e[r]=exp(max_j s[r,j]) into shared,
// writes sum(e) to g_bsum[b], then streams h accumulating
// partial[k] = sum_r e[r]*h[r,k] (k = tid, fully coalesced 4KB/row).
// ---------------------------------------------------------------------------
__global__ __launch_bounds__(1024, 2)
void k_main(const float* __restrict__ h, const float* __restrict__ s) {
    __shared__ float e_sh[64];   // nrows <= ceil(16384/296) = 56

    const int b    = blockIdx.x;
    const int t0   = (int)(((long long)b       * T_LEN) / GRID1);
    const int t1   = (int)(((long long)(b + 1) * T_LEN) / GRID1);
    const int nrows = t1 - t0;
    const int tid  = threadIdx.x;
    const int w    = tid >> 5;
    const int lane = tid & 31;

    // Phase A: warp-per-row max over J=64 (each lane reads a float2 -> 256B/row)
    for (int r = w; r < nrows; r += 32) {
        const float2 v = *reinterpret_cast<const float2*>(
            s + (size_t)(t0 + r) * J_LEN + lane * 2);
        float m = fmaxf(v.x, v.y);
        #pragma unroll
        for (int off = 16; off > 0; off >>= 1)
            m = fmaxf(m, __shfl_xor_sync(0xFFFFFFFFu, m, off));
        if (lane == 0) e_sh[r] = expf(m);
    }
    __syncthreads();

    // Phase B: block's exp-sum -> g_bsum[b] (warp 0 only, no atomics)
    if (w == 0) {
        float bs = 0.0f;
        for (int r = lane; r < nrows; r += 32) bs += e_sh[r];
        #pragma unroll
        for (int off = 16; off > 0; off >>= 1)
            bs += __shfl_xor_sync(0xFFFFFFFFu, bs, off);
        if (lane == 0) g_bsum[b] = bs;
    }

    // Phase C: stream h rows, accumulate weighted sum per column k = tid
    float acc = 0.0f;
    const float* __restrict__ hp = h + (size_t)t0 * D_LEN + tid;
    #pragma unroll 4
    for (int r = 0; r < nrows; r++)
        acc = fmaf(e_sh[r], __ldg(hp + (size_t)r * D_LEN), acc);

    g_partial[b * D_LEN + tid] = acc;
}

// ---------------------------------------------------------------------------
// Kernel 2: per-k reduction of partials + softmax normalize + broadcast row.
// Block k reduces 296 partials & 296 bsums (L2-resident), then writes
// out[k, 0..T) = ctx_k / S with float4 streaming stores (64KB/block).
// ---------------------------------------------------------------------------
__global__ __launch_bounds__(512)
void k_out(float4* __restrict__ out) {
    __shared__ float shp[512];
    __shared__ float shs[512];

    const int k   = blockIdx.x;
    const int tid = threadIdx.x;

    shp[tid] = (tid < GRID1) ? g_partial[tid * D_LEN + k] : 0.0f;
    shs[tid] = (tid < GRID1) ? g_bsum[tid]                : 0.0f;
    __syncthreads();

    #pragma unroll
    for (int off = 256; off > 0; off >>= 1) {
        if (tid < off) {
            shp[tid] += shp[tid + off];
            shs[tid] += shs[tid + off];
        }
        __syncthreads();
    }

    const float v = shp[0] / shs[0];
    const float4 vv = make_float4(v, v, v, v);
    float4* __restrict__ row = out + (size_t)k * (T_LEN / 4);
    #pragma unroll
    for (int j = 0; j < (T_LEN / 4) / 512; j++)   // 8 stores/thread
        row[j * 512 + tid] = vv;
}

// ---------------------------------------------------------------------------
extern "C" void kernel_launch(void* const* d_in, const int* in_sizes, int n_in,
                              void* d_out, int out_size) {
    const float* h = (const float*)d_in[0];   // [1, T, d]
    const float* s = (const float*)d_in[1];   // [T, J]
    float* out = (float*)d_out;               // [d, T]

    k_main<<<GRID1, 1024>>>(h, s);
    k_out<<<D_LEN, 512>>>((float4*)out);
}

// round 4
// speedup vs baseline: 1.3167x; 1.1242x over previous
#include <cuda_runtime.h>
#include <cuda_bf16.h>

// Problem constants (Query2Context_15539191677614)
#define T_LEN 16384
#define J_LEN 64
#define D_LEN 1024
#define GRID1 296   // 2 CTAs per SM (148 SMs), balanced row split

// Scratch (no cudaMalloc allowed; overwritten every replay -> deterministic)
__device__ float g_partial[GRID1 * D_LEN];  // per-block ctx partials
__device__ float g_bsum[GRID1];             // per-block exp sums

// ---------------------------------------------------------------------------
// Kernel 1: fused rowmax/exp + weighted-sum partials.
// Block b owns rows [t0, t1): computes e[r]=exp(max_j s[r,j]) into shared,
// writes sum(e) to g_bsum[b], then streams h accumulating
// partial[k] = sum_r e[r]*h[r,k] (k = tid, fully coalesced 4KB/row).
// All streaming reads use __ldcs (evict-first) to keep L2 clean.
// ---------------------------------------------------------------------------
__global__ __launch_bounds__(1024, 2)
void k_main(const float* __restrict__ h, const float* __restrict__ s) {
    __shared__ float e_sh[64];   // nrows <= ceil(16384/296) = 56

    const int b     = blockIdx.x;
    const int t0    = (int)(((long long)b       * T_LEN) / GRID1);
    const int t1    = (int)(((long long)(b + 1) * T_LEN) / GRID1);
    const int nrows = t1 - t0;
    const int tid   = threadIdx.x;
    const int w     = tid >> 5;
    const int lane  = tid & 31;

    // Phase A: warp-per-row max over J=64 (each lane reads a float2 -> 256B/row)
    for (int r = w; r < nrows; r += 32) {
        const float2* p = reinterpret_cast<const float2*>(
            s + (size_t)(t0 + r) * J_LEN + lane * 2);
        const float2 v = __ldcs(p);
        float m = fmaxf(v.x, v.y);
        #pragma unroll
        for (int off = 16; off > 0; off >>= 1)
            m = fmaxf(m, __shfl_xor_sync(0xFFFFFFFFu, m, off));
        if (lane == 0) e_sh[r] = expf(m);
    }
    __syncthreads();

    // Phase B: block's exp-sum -> g_bsum[b] (warp 0 only, no atomics)
    if (w == 0) {
        float bs = 0.0f;
        for (int r = lane; r < nrows; r += 32) bs += e_sh[r];
        #pragma unroll
        for (int off = 16; off > 0; off >>= 1)
            bs += __shfl_xor_sync(0xFFFFFFFFu, bs, off);
        if (lane == 0) g_bsum[b] = bs;
    }

    // Phase C: stream h rows, accumulate weighted sum per column k = tid
    float acc = 0.0f;
    const float* __restrict__ hp = h + (size_t)t0 * D_LEN + tid;
    #pragma unroll 4
    for (int r = 0; r < nrows; r++)
        acc = fmaf(e_sh[r], __ldcs(hp + (size_t)r * D_LEN), acc);

    g_partial[b * D_LEN + tid] = acc;
}

// ---------------------------------------------------------------------------
// Kernel 2: per-k reduction of partials + softmax normalize + broadcast row.
// Block k reduces 296 partials & 296 bsums (L2-resident), then writes
// out[k, 0..T) = ctx_k / S with WRITE-THROUGH float4 stores (__stwt) so the
// 64MB lands in DRAM during THIS kernel's window instead of dirtying L2 and
// taxing the next replay's k_main with writeback evictions.
// ---------------------------------------------------------------------------
__global__ __launch_bounds__(512)
void k_out(float4* __restrict__ out) {
    __shared__ float shp[512];
    __shared__ float shs[512];

    const int k   = blockIdx.x;
    const int tid = threadIdx.x;

    shp[tid] = (tid < GRID1) ? g_partial[tid * D_LEN + k] : 0.0f;
    shs[tid] = (tid < GRID1) ? g_bsum[tid]                : 0.0f;
    __syncthreads();

    #pragma unroll
    for (int off = 256; off > 0; off >>= 1) {
        if (tid < off) {
            shp[tid] += shp[tid + off];
            shs[tid] += shs[tid + off];
        }
        __syncthreads();
    }

    const float v = shp[0] / shs[0];
    const float4 vv = make_float4(v, v, v, v);
    float4* __restrict__ row = out + (size_t)k * (T_LEN / 4);
    #pragma unroll
    for (int j = 0; j < (T_LEN / 4) / 512; j++)   // 8 stores/thread
        __stwt(row + j * 512 + tid, vv);
}

// ---------------------------------------------------------------------------
extern "C" void kernel_launch(void* const* d_in, const int* in_sizes, int n_in,
                              void* d_out, int out_size) {
    const float* h = (const float*)d_in[0];   // [1, T, d]
    const float* s = (const float*)d_in[1];   // [T, J]
    float* out = (float*)d_out;               // [d, T]

    k_main<<<GRID1, 1024>>>(h, s);
    k_out<<<D_LEN, 512>>>((float4*)out);
}